// round 11
// baseline (speedup 1.0000x reference)
#include <cuda_runtime.h>
#include <math.h>
#include <stdint.h>

// XSReLU_cw_perc_param: out = relu(x - thr[b,c]),
//   thr = s[k_lo] + (s[k_hi] - s[k_lo]) * sigmoid(plogit[c])
//   where s = sorted row of x[b,c,:,:] (4096 elems), and
//   k_lo = clip((int)(4096*(p0-0.02)),0,4095), k_hi = clip((int)(4096*(p0+0.02)),0,4095),
//   p0 = sigmoid(plogit[0]).
// Only two order statistics are needed -> per-row dual radix select, no sort.

#define ROW_LEN   4096
#define THREADS   256
#define PER_THR   16          // ROW_LEN / THREADS

__device__ __forceinline__ unsigned f2s(float f) {
    unsigned u = __float_as_uint(f);
    return (u & 0x80000000u) ? ~u : (u | 0x80000000u);
}
__device__ __forceinline__ float s2f(unsigned u) {
    u = (u & 0x80000000u) ? (u ^ 0x80000000u) : ~u;
    return __uint_as_float(u);
}

__global__ void __launch_bounds__(THREADS)
XSReLU_cw_perc_param_47528108097997_kernel(const float* __restrict__ x,
                                           const float* __restrict__ plogit,
                                           float* __restrict__ out, int C) {
    const int row  = blockIdx.x;          // 0 .. B*C-1
    const int tid  = threadIdx.x;
    const int lane = tid & 31;
    const int wid  = tid >> 5;

    __shared__ unsigned hist[256];
    __shared__ unsigned warp_sums[8];
    __shared__ unsigned sel[4];           // digitLo, rankLo', digitHi, rankHi'

    const float4* __restrict__ xr =
        reinterpret_cast<const float4*>(x) + (size_t)row * (ROW_LEN / 4);
    float4* __restrict__ orow =
        reinterpret_cast<float4*>(out) + (size_t)row * (ROW_LEN / 4);

    // ---- load row into registers (coalesced float4), convert to sortable uints
    float4   v[4];
    unsigned u[PER_THR];
    #pragma unroll
    for (int j = 0; j < 4; ++j) {
        float4 t = xr[tid + j * THREADS];
        v[j] = t;
        u[4 * j + 0] = f2s(t.x);
        u[4 * j + 1] = f2s(t.y);
        u[4 * j + 2] = f2s(t.z);
        u[4 * j + 3] = f2s(t.w);
    }

    // ---- ranks (scalar, from plogit[0]); match jnp f32 arithmetic + trunc cast
    const float p0 = 1.0f / (1.0f + expf(-plogit[0]));
    int kLoI = (int)(4096.0f * (p0 - 0.02f));
    int kHiI = (int)(4096.0f * (p0 + 0.02f));
    kLoI = min(max(kLoI, 0), ROW_LEN - 1);
    kHiI = min(max(kHiI, 0), ROW_LEN - 1);
    unsigned rLo = (unsigned)kLoI;
    unsigned rHi = (unsigned)kHiI;

    // ================= pass 0: top byte, shared by both ranks =================
    hist[tid] = 0;
    __syncthreads();
    #pragma unroll
    for (int j = 0; j < PER_THR; ++j) {
        unsigned d = u[j] >> 24;
        // warp-aggregated atomic: Gaussian data makes top-byte bins very hot
        unsigned m      = __match_any_sync(0xffffffffu, d);
        unsigned leader = __ffs(m) - 1u;
        if (lane == (int)leader) atomicAdd(&hist[d], (unsigned)__popc(m));
    }
    __syncthreads();

    {
        unsigned h   = hist[tid];
        unsigned inc = h;
        #pragma unroll
        for (int s = 1; s < 32; s <<= 1) {
            unsigned n = __shfl_up_sync(0xffffffffu, inc, s);
            if (lane >= s) inc += n;
        }
        if (lane == 31) warp_sums[wid] = inc;
        __syncthreads();
        unsigned off = 0;
        #pragma unroll
        for (int w = 0; w < 8; ++w)
            if (w < wid) off += warp_sums[w];
        unsigned excl = off + inc - h;
        if (rLo >= excl && rLo < excl + h) { sel[0] = (unsigned)tid; sel[1] = rLo - excl; }
        if (rHi >= excl && rHi < excl + h) { sel[2] = (unsigned)tid; sel[3] = rHi - excl; }
        __syncthreads();
    }
    unsigned pfxLo = sel[0] << 24;  rLo = sel[1];
    unsigned pfxHi = sel[2] << 24;  rHi = sel[3];

    // ============ passes 1..3: dual select with packed 16|16 histogram ========
    #pragma unroll 1
    for (int shift = 16; shift >= 0; shift -= 8) {
        __syncthreads();              // everyone has consumed sel from prev pass
        hist[tid] = 0;
        __syncthreads();
        const int      ms  = shift + 8;
        const unsigned tLo = pfxLo >> ms;
        const unsigned tHi = pfxHi >> ms;
        #pragma unroll
        for (int j = 0; j < PER_THR; ++j) {
            unsigned uj  = u[j];
            unsigned top = uj >> ms;
            unsigned add = 0;
            if (top == tLo) add += 1u;
            if (top == tHi) add += 0x10000u;
            if (add) atomicAdd(&hist[(uj >> shift) & 0xFFu], add);
        }
        __syncthreads();

        unsigned h   = hist[tid];
        unsigned inc = h;                       // packed scan; each field <= 4096
        #pragma unroll
        for (int s = 1; s < 32; s <<= 1) {
            unsigned n = __shfl_up_sync(0xffffffffu, inc, s);
            if (lane >= s) inc += n;
        }
        if (lane == 31) warp_sums[wid] = inc;
        __syncthreads();
        unsigned off = 0;
        #pragma unroll
        for (int w = 0; w < 8; ++w)
            if (w < wid) off += warp_sums[w];
        unsigned excl = off + inc - h;

        unsigned exLo = excl & 0xFFFFu, hLo = h & 0xFFFFu;
        unsigned exHi = excl >> 16,     hHi = h >> 16;
        if (rLo >= exLo && rLo < exLo + hLo) { sel[0] = (unsigned)tid; sel[1] = rLo - exLo; }
        if (rHi >= exHi && rHi < exHi + hHi) { sel[2] = (unsigned)tid; sel[3] = rHi - exHi; }
        __syncthreads();
        pfxLo |= sel[0] << shift;  rLo = sel[1];
        pfxHi |= sel[2] << shift;  rHi = sel[3];
    }

    // ---- threshold and fused epilogue (single HBM read already done)
    const float xl = s2f(pfxLo);
    const float xh = s2f(pfxHi);
    const float pc = 1.0f / (1.0f + expf(-plogit[row % C]));
    const float thr = xl + (xh - xl) * pc;

    #pragma unroll
    for (int j = 0; j < 4; ++j) {
        float4 t = v[j];
        t.x = fmaxf(t.x - thr, 0.0f);
        t.y = fmaxf(t.y - thr, 0.0f);
        t.z = fmaxf(t.z - thr, 0.0f);
        t.w = fmaxf(t.w - thr, 0.0f);
        orow[tid + j * THREADS] = t;
    }
}

extern "C" void kernel_launch(void* const* d_in, const int* in_sizes, int n_in,
                              void* d_out, int out_size) {
    const float* x      = (const float*)d_in[0];   // [B, C, H, W] f32
    const float* plogit = (const float*)d_in[1];   // [C] f32
    float*       out    = (float*)d_out;

    const int total = in_sizes[0];                 // B*C*H*W = 33,554,432
    const int C     = in_sizes[1];                 // 256
    const int rows  = total / ROW_LEN;             // B*C = 8192

    XSReLU_cw_perc_param_47528108097997_kernel<<<rows, THREADS>>>(x, plogit, out, C);
}